// round 2
// baseline (speedup 1.0000x reference)
#include <cuda_runtime.h>

// Problem constants (fixed shapes from reference)
#define C_DIM   512
#define HEADS   16
#define HD      32
#define BATCH   8
#define IMG     32
#define NTOK    1024            // IMG*IMG
#define MROWS   (BATCH * NTOK)  // 8192
#define QKVW    (3 * C_DIM)     // 1536

// Scratch (static device globals; allocation-free per harness rules)
__device__ float g_qkv [(size_t)MROWS * QKVW];   // ~50 MB
__device__ float g_attn[(size_t)MROWS * C_DIM];  // ~17 MB
__device__ float g_lepe[(size_t)MROWS * C_DIM];  // ~17 MB

// ---------------------------------------------------------------------------
// SGEMM (NT): C[m,n] = sum_k (A[m,k] + A2[m,k]) * W[n,k] + bias[n]
// A: [M,K] row-major, W: [N,K] row-major (torch Linear weight layout).
// BM=BN=128, BK=8, 256 threads, 8x8 per thread. Double-buffered smem:
// one __syncthreads per K-step; global prefetch overlaps the FMA loop.
// M, N multiples of 128; K multiple of 8 (true for all our calls).
// ---------------------------------------------------------------------------
__global__ __launch_bounds__(256) void sgemm_nt(
    const float* __restrict__ A, const float* __restrict__ A2,
    const float* __restrict__ W, const float* __restrict__ bias,
    float* __restrict__ C, int M, int Nn, int K)
{
    __shared__ float As[2][8][128];
    __shared__ float Bs[2][8][128];

    const int tid = threadIdx.x;
    const int tx  = tid & 15;        // 0..15 -> column group
    const int ty  = tid >> 4;        // 0..15 -> row group
    const int m0  = blockIdx.y * 128;
    const int n0  = blockIdx.x * 128;

    const int lr = tid >> 1;         // load row 0..127
    const int lc = (tid & 1) * 4;    // load col 0 or 4

    const float* Aptr  = A + (size_t)(m0 + lr) * K + lc;
    const float* A2ptr = A2 ? (A2 + (size_t)(m0 + lr) * K + lc) : nullptr;
    const float* Wptr  = W + (size_t)(n0 + lr) * K + lc;

    float acc[8][8];
#pragma unroll
    for (int i = 0; i < 8; i++)
#pragma unroll
        for (int j = 0; j < 8; j++) acc[i][j] = 0.f;

    // --- Prologue: fetch tile 0 into buffer 0 ---
    {
        float4 a = *(const float4*)(Aptr);
        if (A2ptr) {
            float4 a2 = *(const float4*)(A2ptr);
            a.x += a2.x; a.y += a2.y; a.z += a2.z; a.w += a2.w;
        }
        float4 w = *(const float4*)(Wptr);
        As[0][lc + 0][lr] = a.x; As[0][lc + 1][lr] = a.y;
        As[0][lc + 2][lr] = a.z; As[0][lc + 3][lr] = a.w;
        Bs[0][lc + 0][lr] = w.x; Bs[0][lc + 1][lr] = w.y;
        Bs[0][lc + 2][lr] = w.z; Bs[0][lc + 3][lr] = w.w;
    }
    __syncthreads();

    int cur = 0;
    for (int k0 = 8; k0 <= K; k0 += 8) {
        // Prefetch next tile (overlaps with compute below)
        float4 an, wn;
        const bool has_next = (k0 < K);
        if (has_next) {
            an = *(const float4*)(Aptr + k0);
            if (A2ptr) {
                float4 a2 = *(const float4*)(A2ptr + k0);
                an.x += a2.x; an.y += a2.y; an.z += a2.z; an.w += a2.w;
            }
            wn = *(const float4*)(Wptr + k0);
        }

        // Compute on current buffer
#pragma unroll
        for (int kk = 0; kk < 8; kk++) {
            float4 a0 = *(const float4*)&As[cur][kk][ty * 8];
            float4 a1 = *(const float4*)&As[cur][kk][ty * 8 + 4];
            float4 b0 = *(const float4*)&Bs[cur][kk][tx * 4];
            float4 b1 = *(const float4*)&Bs[cur][kk][64 + tx * 4];
            float av[8] = {a0.x, a0.y, a0.z, a0.w, a1.x, a1.y, a1.z, a1.w};
            float bv[8] = {b0.x, b0.y, b0.z, b0.w, b1.x, b1.y, b1.z, b1.w};
#pragma unroll
            for (int i = 0; i < 8; i++)
#pragma unroll
                for (int j = 0; j < 8; j++)
                    acc[i][j] += av[i] * bv[j];
        }

        if (has_next) {
            const int nxt = cur ^ 1;
            As[nxt][lc + 0][lr] = an.x; As[nxt][lc + 1][lr] = an.y;
            As[nxt][lc + 2][lr] = an.z; As[nxt][lc + 3][lr] = an.w;
            Bs[nxt][lc + 0][lr] = wn.x; Bs[nxt][lc + 1][lr] = wn.y;
            Bs[nxt][lc + 2][lr] = wn.z; Bs[nxt][lc + 3][lr] = wn.w;
            __syncthreads();
            cur = nxt;
        }
    }

    // --- Epilogue: vectorized stores (two STG.128 per row) ---
    float4 bias0 = make_float4(0.f, 0.f, 0.f, 0.f);
    float4 bias1 = bias0;
    if (bias) {
        bias0 = *(const float4*)(bias + n0 + tx * 4);
        bias1 = *(const float4*)(bias + n0 + 64 + tx * 4);
    }
#pragma unroll
    for (int i = 0; i < 8; i++) {
        const int row = m0 + ty * 8 + i;
        float* Crow = C + (size_t)row * Nn + n0;
        float4 o0 = make_float4(acc[i][0] + bias0.x, acc[i][1] + bias0.y,
                                acc[i][2] + bias0.z, acc[i][3] + bias0.w);
        float4 o1 = make_float4(acc[i][4] + bias1.x, acc[i][5] + bias1.y,
                                acc[i][6] + bias1.z, acc[i][7] + bias1.w);
        *(float4*)(Crow + tx * 4)      = o0;
        *(float4*)(Crow + 64 + tx * 4) = o1;
    }
}

// ---------------------------------------------------------------------------
// Flash attention, fp32. One block = (batch b, head h, 128-query tile).
// 128 threads, 1 query row per thread; K/V tiles of 128 keys in smem.
// qkv row layout: [q(512) | k(512) | v(512)], head slice = h*32..h*32+31.
// Output written directly in [B, N, C] layout (matches transpose+reshape).
// ---------------------------------------------------------------------------
__global__ __launch_bounds__(128) void attn_kernel(
    const float* __restrict__ qkv, float* __restrict__ out)
{
    __shared__ float4 ks[128 * 8];
    __shared__ float4 vs[128 * 8];

    const int blk = blockIdx.x;
    const int qt  = blk & 7;          // query tile 0..7
    const int h   = (blk >> 3) & 15;  // head
    const int b   = blk >> 7;         // batch
    const int tid = threadIdx.x;
    const int qrow = qt * 128 + tid;

    const float* base = qkv + (size_t)b * NTOK * QKVW;

    const float scale = 0.17677669529663687f;  // 32^-0.5
    float4 q[8];
    {
        const float4* qp = (const float4*)(base + (size_t)qrow * QKVW + h * HD);
#pragma unroll
        for (int i = 0; i < 8; i++) {
            float4 t = qp[i];
            q[i] = make_float4(t.x * scale, t.y * scale, t.z * scale, t.w * scale);
        }
    }

    float m = -1e30f, l = 0.f;
    float acc[32];
#pragma unroll
    for (int d = 0; d < 32; d++) acc[d] = 0.f;

    for (int t = 0; t < 8; t++) {
        __syncthreads();
#pragma unroll
        for (int it = 0; it < 8; it++) {
            int f = tid + it * 128;
            int r = f >> 3, c = f & 7;
            const float* rowp = base + (size_t)(t * 128 + r) * QKVW + h * HD + c * 4;
            ks[f] = *(const float4*)(rowp + C_DIM);
            vs[f] = *(const float4*)(rowp + 2 * C_DIM);
        }
        __syncthreads();

        for (int j0 = 0; j0 < 128; j0 += 16) {
            float s[16];
#pragma unroll
            for (int j = 0; j < 16; j++) {
                const float4* kr = &ks[(j0 + j) * 8];
                float v0 = 0.f;
#pragma unroll
                for (int d = 0; d < 8; d++) {
                    float4 kk = kr[d];  // warp-broadcast LDS.128
                    v0 += q[d].x * kk.x + q[d].y * kk.y
                        + q[d].z * kk.z + q[d].w * kk.w;
                }
                s[j] = v0;
            }
            float mt = m;
#pragma unroll
            for (int j = 0; j < 16; j++) mt = fmaxf(mt, s[j]);
            float corr = __expf(m - mt);
            m = mt;
            l *= corr;
#pragma unroll
            for (int d = 0; d < 32; d++) acc[d] *= corr;
#pragma unroll
            for (int j = 0; j < 16; j++) {
                float p = __expf(s[j] - m);
                l += p;
                const float4* vr = &vs[(j0 + j) * 8];
#pragma unroll
                for (int d = 0; d < 8; d++) {
                    float4 vv = vr[d];
                    acc[d * 4 + 0] += p * vv.x;
                    acc[d * 4 + 1] += p * vv.y;
                    acc[d * 4 + 2] += p * vv.z;
                    acc[d * 4 + 3] += p * vv.w;
                }
            }
        }
    }

    const float inv = 1.f / l;
    float* op = out + (size_t)(b * NTOK + qrow) * C_DIM + h * HD;
#pragma unroll
    for (int d = 0; d < 8; d++) {
        float4 o = make_float4(acc[d * 4 + 0] * inv, acc[d * 4 + 1] * inv,
                               acc[d * 4 + 2] * inv, acc[d * 4 + 3] * inv);
        *(float4*)(op + d * 4) = o;
    }
}

// ---------------------------------------------------------------------------
// LePE: 5x5 depthwise conv on x (NHWC), zero padding, output in [B,N,C].
// grid = (B*IMG*IMG, 2); 256 threads cover 256 channels each.
// Weights staged in smem; stride-25 reads are bank-conflict-free (gcd(25,32)=1).
// ---------------------------------------------------------------------------
__global__ __launch_bounds__(256) void lepe_kernel(
    const float* __restrict__ x, const float* __restrict__ w,
    const float* __restrict__ bias, float* __restrict__ out)
{
    __shared__ float ws[256 * 25];
    const int tid = threadIdx.x;
    const int c0  = blockIdx.y * 256;
    for (int i = tid; i < 256 * 25; i += 256) ws[i] = w[c0 * 25 + i];
    __syncthreads();

    const int pos = blockIdx.x;
    const int c   = c0 + tid;
    const int b   = pos >> 10;
    const int y   = (pos >> 5) & 31;
    const int xx  = pos & 31;
    const float* wv = &ws[tid * 25];

    float acc = bias[c];
#pragma unroll
    for (int dy = 0; dy < 5; dy++) {
        const int yy = y + dy - 2;
        if ((unsigned)yy >= 32u) continue;
#pragma unroll
        for (int dx = 0; dx < 5; dx++) {
            const int xs = xx + dx - 2;
            if ((unsigned)xs >= 32u) continue;
            acc += x[(((size_t)b * IMG + yy) * IMG + xs) * C_DIM + c] * wv[dy * 5 + dx];
        }
    }
    out[(size_t)pos * C_DIM + c] = acc;
}

// ---------------------------------------------------------------------------
// Launch: qkv GEMM -> attention ; lepe (independent) ; fused (attn+lepe) proj
// All on one stream -> correct ordering under graph capture.
// ---------------------------------------------------------------------------
extern "C" void kernel_launch(void* const* d_in, const int* in_sizes, int n_in,
                              void* d_out, int out_size)
{
    const float* x      = (const float*)d_in[0];
    const float* w_qkv  = (const float*)d_in[1];
    const float* w_proj = (const float*)d_in[2];
    const float* b_proj = (const float*)d_in[3];
    const float* w_lepe = (const float*)d_in[4];
    const float* b_lepe = (const float*)d_in[5];
    float* out = (float*)d_out;

    float *qkv_buf, *attn_buf, *lepe_buf;
    cudaGetSymbolAddress((void**)&qkv_buf,  g_qkv);
    cudaGetSymbolAddress((void**)&attn_buf, g_attn);
    cudaGetSymbolAddress((void**)&lepe_buf, g_lepe);

    // 1) QKV GEMM: [8192,512] x [1536,512]^T -> [8192,1536]
    sgemm_nt<<<dim3(QKVW / 128, MROWS / 128), 256>>>(
        x, nullptr, w_qkv, nullptr, qkv_buf, MROWS, QKVW, C_DIM);

    // 2) Flash attention -> g_attn in [B,N,C] layout
    attn_kernel<<<BATCH * HEADS * (NTOK / 128), 128>>>(qkv_buf, attn_buf);

    // 3) LePE depthwise conv -> g_lepe
    lepe_kernel<<<dim3(BATCH * IMG * IMG, C_DIM / 256), 256>>>(
        x, w_lepe, b_lepe, lepe_buf);

    // 4) Fused (attn + lepe) @ w_proj^T + b_proj -> out
    sgemm_nt<<<dim3(C_DIM / 128, MROWS / 128), 256>>>(
        attn_buf, lepe_buf, w_proj, b_proj, out, MROWS, C_DIM, C_DIM);
}

// round 7
// speedup vs baseline: 2.0850x; 2.0850x over previous
#include <cuda_runtime.h>
#include <cstdint>

// Problem constants (fixed shapes from reference)
#define C_DIM   512
#define HEADS   16
#define HD      32
#define BATCH   8
#define IMG     32
#define NTOK    1024            // IMG*IMG
#define MROWS   (BATCH * NTOK)  // 8192
#define QKVW    (3 * C_DIM)     // 1536

// Scratch (static device globals; allocation-free per harness rules)
__device__ float g_qkv [(size_t)MROWS * QKVW];   // ~50 MB
__device__ float g_attn[(size_t)MROWS * C_DIM];  // ~17 MB
__device__ float g_lepe[(size_t)MROWS * C_DIM];  // ~17 MB

// ---------------------------------------------------------------------------
// tf32 helpers
// ---------------------------------------------------------------------------
__device__ __forceinline__ uint32_t f2tf32(float f) {
    uint32_t u;
    asm("cvt.rna.tf32.f32 %0, %1;" : "=r"(u) : "f"(f));
    return u;
}
__device__ __forceinline__ float tf32r(float f) {
    return __uint_as_float(f2tf32(f));
}

__device__ __forceinline__ void mma_tf32(float* d, const uint32_t* a,
                                         uint32_t b0, uint32_t b1) {
    asm("mma.sync.aligned.m16n8k8.row.col.f32.tf32.tf32.f32 "
        "{%0,%1,%2,%3}, {%4,%5,%6,%7}, {%8,%9}, {%0,%1,%2,%3};"
        : "+f"(d[0]), "+f"(d[1]), "+f"(d[2]), "+f"(d[3])
        : "r"(a[0]), "r"(a[1]), "r"(a[2]), "r"(a[3]), "r"(b0), "r"(b1));
}

// ---------------------------------------------------------------------------
// TF32 tensor-core GEMM (NT): C[m,n] = sum_k A[m,k] * W[n,k]
// Used for the QKV projection (error-diluted stage; no bias, no A2).
// 256 threads = 8 warps (4 m x 2 n), warp tile 32x64, block tile 128x128.
// BK=16, double-buffered smem stored K-major [k][m], stride 136
// (136 % 32 == 8 -> fragment loads hit 32 distinct banks).
// ---------------------------------------------------------------------------
__global__ __launch_bounds__(256) void sgemm_tf32(
    const float* __restrict__ A, const float* __restrict__ W,
    float* __restrict__ C, int M, int Nn, int K)
{
    __shared__ float As[2][16][136];
    __shared__ float Bs[2][16][136];

    const int tid  = threadIdx.x;
    const int warp = tid >> 5, lane = tid & 31;
    const int g = lane >> 2, tg = lane & 3;
    const int wm = warp & 3, wn = warp >> 2;
    const int m0 = blockIdx.y * 128, n0 = blockIdx.x * 128;

    const int lr = tid >> 1;          // 0..127
    const int lk = (tid & 1) * 8;     // 0 or 8

    const float* Aptr = A + (size_t)(m0 + lr) * K + lk;
    const float* Wptr = W + (size_t)(n0 + lr) * K + lk;

    float acc[2][8][4];
#pragma unroll
    for (int mt = 0; mt < 2; mt++)
#pragma unroll
        for (int nt = 0; nt < 8; nt++)
#pragma unroll
            for (int r = 0; r < 4; r++) acc[mt][nt][r] = 0.f;

#define STASH(buf, a0v, a1v, w0v, w1v)                                   \
    do {                                                                 \
        As[buf][lk + 0][lr] = tf32r((a0v).x);                            \
        As[buf][lk + 1][lr] = tf32r((a0v).y);                            \
        As[buf][lk + 2][lr] = tf32r((a0v).z);                            \
        As[buf][lk + 3][lr] = tf32r((a0v).w);                            \
        As[buf][lk + 4][lr] = tf32r((a1v).x);                            \
        As[buf][lk + 5][lr] = tf32r((a1v).y);                            \
        As[buf][lk + 6][lr] = tf32r((a1v).z);                            \
        As[buf][lk + 7][lr] = tf32r((a1v).w);                            \
        Bs[buf][lk + 0][lr] = tf32r((w0v).x);                            \
        Bs[buf][lk + 1][lr] = tf32r((w0v).y);                            \
        Bs[buf][lk + 2][lr] = tf32r((w0v).z);                            \
        Bs[buf][lk + 3][lr] = tf32r((w0v).w);                            \
        Bs[buf][lk + 4][lr] = tf32r((w1v).x);                            \
        Bs[buf][lk + 5][lr] = tf32r((w1v).y);                            \
        Bs[buf][lk + 6][lr] = tf32r((w1v).z);                            \
        Bs[buf][lk + 7][lr] = tf32r((w1v).w);                            \
    } while (0)

    {
        float4 a0 = *(const float4*)(Aptr);
        float4 a1 = *(const float4*)(Aptr + 4);
        float4 w0 = *(const float4*)(Wptr);
        float4 w1 = *(const float4*)(Wptr + 4);
        STASH(0, a0, a1, w0, w1);
    }
    __syncthreads();

    int cur = 0;
    for (int k0 = 16; k0 <= K; k0 += 16) {
        const bool more = (k0 < K);
        float4 a0, a1, w0, w1;
        if (more) {
            a0 = *(const float4*)(Aptr + k0);
            a1 = *(const float4*)(Aptr + k0 + 4);
            w0 = *(const float4*)(Wptr + k0);
            w1 = *(const float4*)(Wptr + k0 + 4);
        }

#pragma unroll
        for (int ks = 0; ks < 2; ks++) {
            const int kr0 = ks * 8 + tg, kr1 = kr0 + 4;
            uint32_t Af[2][4];
#pragma unroll
            for (int mt = 0; mt < 2; mt++) {
                const int mb = wm * 32 + mt * 16;
                Af[mt][0] = __float_as_uint(As[cur][kr0][mb + g]);
                Af[mt][1] = __float_as_uint(As[cur][kr0][mb + g + 8]);
                Af[mt][2] = __float_as_uint(As[cur][kr1][mb + g]);
                Af[mt][3] = __float_as_uint(As[cur][kr1][mb + g + 8]);
            }
            uint32_t Bf[8][2];
#pragma unroll
            for (int nt = 0; nt < 8; nt++) {
                const int cb = wn * 64 + nt * 8 + g;
                Bf[nt][0] = __float_as_uint(Bs[cur][kr0][cb]);
                Bf[nt][1] = __float_as_uint(Bs[cur][kr1][cb]);
            }
#pragma unroll
            for (int mt = 0; mt < 2; mt++)
#pragma unroll
                for (int nt = 0; nt < 8; nt++)
                    mma_tf32(acc[mt][nt], Af[mt], Bf[nt][0], Bf[nt][1]);
        }

        if (more) {
            STASH(cur ^ 1, a0, a1, w0, w1);
            __syncthreads();
            cur ^= 1;
        }
    }
#undef STASH

    // Epilogue: C-fragment rows g / g+8, cols nt*8 + 2tg (+1)
#pragma unroll
    for (int mt = 0; mt < 2; mt++) {
        const int r0 = m0 + wm * 32 + mt * 16 + g;
        float* c0 = C + (size_t)r0 * Nn + n0 + wn * 64;
        float* c1 = c0 + (size_t)8 * Nn;
#pragma unroll
        for (int nt = 0; nt < 8; nt++) {
            *(float2*)(c0 + nt * 8 + 2 * tg) =
                make_float2(acc[mt][nt][0], acc[mt][nt][1]);
            *(float2*)(c1 + nt * 8 + 2 * tg) =
                make_float2(acc[mt][nt][2], acc[mt][nt][3]);
        }
    }
}

// ---------------------------------------------------------------------------
// 3xTF32 tensor-core GEMM (NT), near-fp32 precision:
//   C[m,n] = sum_k (A[m,k]+A2[m,k]) * W[n,k] + bias[n]
// Each operand split v = hi + lo (hi = tf32(v), lo = tf32(v - hi));
// product approximated as hi*hi + hi*lo + lo*hi (error ~2^-22, negligible).
// Used for proj. Single-buffered smem (hi/lo x A/B = 34.8 KB), BK=16,
// 256 threads = 8 warps (4m x 2n), warp tile 32x64.
// ---------------------------------------------------------------------------
__global__ __launch_bounds__(256) void sgemm_3xtf32(
    const float* __restrict__ A, const float* __restrict__ A2,
    const float* __restrict__ W, const float* __restrict__ bias,
    float* __restrict__ C, int M, int Nn, int K)
{
    __shared__ float Ah[16][136], Al[16][136];
    __shared__ float Bh[16][136], Bl[16][136];

    const int tid  = threadIdx.x;
    const int warp = tid >> 5, lane = tid & 31;
    const int g = lane >> 2, tg = lane & 3;
    const int wm = warp & 3, wn = warp >> 2;
    const int m0 = blockIdx.y * 128, n0 = blockIdx.x * 128;

    const int lr = tid >> 1;          // 0..127
    const int lk = (tid & 1) * 8;     // 0 or 8

    const float* Aptr  = A  + (size_t)(m0 + lr) * K + lk;
    const float* A2ptr = A2 + (size_t)(m0 + lr) * K + lk;
    const float* Wptr  = W  + (size_t)(n0 + lr) * K + lk;

    float acc[2][8][4];
#pragma unroll
    for (int mt = 0; mt < 2; mt++)
#pragma unroll
        for (int nt = 0; nt < 8; nt++)
#pragma unroll
            for (int r = 0; r < 4; r++) acc[mt][nt][r] = 0.f;

    for (int k0 = 0; k0 < K; k0 += 16) {
        // Stage: load 8 A-floats (A+A2) and 8 W-floats per thread, split hi/lo
        float av[8], wv[8];
        {
            float4 x0 = *(const float4*)(Aptr + k0);
            float4 x1 = *(const float4*)(Aptr + k0 + 4);
            float4 y0 = *(const float4*)(A2ptr + k0);
            float4 y1 = *(const float4*)(A2ptr + k0 + 4);
            av[0] = x0.x + y0.x; av[1] = x0.y + y0.y;
            av[2] = x0.z + y0.z; av[3] = x0.w + y0.w;
            av[4] = x1.x + y1.x; av[5] = x1.y + y1.y;
            av[6] = x1.z + y1.z; av[7] = x1.w + y1.w;
            float4 w0 = *(const float4*)(Wptr + k0);
            float4 w1 = *(const float4*)(Wptr + k0 + 4);
            wv[0] = w0.x; wv[1] = w0.y; wv[2] = w0.z; wv[3] = w0.w;
            wv[4] = w1.x; wv[5] = w1.y; wv[6] = w1.z; wv[7] = w1.w;
        }
        __syncthreads();   // previous tile fully consumed
#pragma unroll
        for (int i = 0; i < 8; i++) {
            float ahi = tf32r(av[i]);
            float whi = tf32r(wv[i]);
            Ah[lk + i][lr] = ahi;
            Al[lk + i][lr] = tf32r(av[i] - ahi);
            Bh[lk + i][lr] = whi;
            Bl[lk + i][lr] = tf32r(wv[i] - whi);
        }
        __syncthreads();

#pragma unroll
        for (int ks = 0; ks < 2; ks++) {
            const int kr0 = ks * 8 + tg, kr1 = kr0 + 4;
            uint32_t Afh[2][4], Afl[2][4];
#pragma unroll
            for (int mt = 0; mt < 2; mt++) {
                const int mb = wm * 32 + mt * 16;
                Afh[mt][0] = __float_as_uint(Ah[kr0][mb + g]);
                Afh[mt][1] = __float_as_uint(Ah[kr0][mb + g + 8]);
                Afh[mt][2] = __float_as_uint(Ah[kr1][mb + g]);
                Afh[mt][3] = __float_as_uint(Ah[kr1][mb + g + 8]);
                Afl[mt][0] = __float_as_uint(Al[kr0][mb + g]);
                Afl[mt][1] = __float_as_uint(Al[kr0][mb + g + 8]);
                Afl[mt][2] = __float_as_uint(Al[kr1][mb + g]);
                Afl[mt][3] = __float_as_uint(Al[kr1][mb + g + 8]);
            }
#pragma unroll
            for (int nt = 0; nt < 8; nt++) {
                const int cb = wn * 64 + nt * 8 + g;
                uint32_t bh0 = __float_as_uint(Bh[kr0][cb]);
                uint32_t bh1 = __float_as_uint(Bh[kr1][cb]);
                uint32_t bl0 = __float_as_uint(Bl[kr0][cb]);
                uint32_t bl1 = __float_as_uint(Bl[kr1][cb]);
#pragma unroll
                for (int mt = 0; mt < 2; mt++) {
                    mma_tf32(acc[mt][nt], Afl[mt], bh0, bh1);  // lo*hi
                    mma_tf32(acc[mt][nt], Afh[mt], bl0, bl1);  // hi*lo
                    mma_tf32(acc[mt][nt], Afh[mt], bh0, bh1);  // hi*hi
                }
            }
        }
    }

    // Epilogue with bias
#pragma unroll
    for (int mt = 0; mt < 2; mt++) {
        const int r0 = m0 + wm * 32 + mt * 16 + g;
        float* c0 = C + (size_t)r0 * Nn + n0 + wn * 64;
        float* c1 = c0 + (size_t)8 * Nn;
#pragma unroll
        for (int nt = 0; nt < 8; nt++) {
            const int cc = n0 + wn * 64 + nt * 8 + 2 * tg;
            float b0v = bias[cc], b1v = bias[cc + 1];
            *(float2*)(c0 + nt * 8 + 2 * tg) =
                make_float2(acc[mt][nt][0] + b0v, acc[mt][nt][1] + b1v);
            *(float2*)(c1 + nt * 8 + 2 * tg) =
                make_float2(acc[mt][nt][2] + b0v, acc[mt][nt][3] + b1v);
        }
    }
}

// ---------------------------------------------------------------------------
// Flash attention on tf32 tensor cores (mma.sync m16n8k8).
// Block = (b, h, 128-query tile); 4 warps x 32 query rows.
// K stored transposed [dim][key] stride 72 (conflict-free B frags),
// V natural [key][dim] stride 40 (conflict-free B frags),
// P staged per-warp [row][key] stride 36 (conflict-free A frags).
// fragment layout (m16n8k8): g=lane>>2, tg=lane&3
//   A: a0(g,tg) a1(g+8,tg) a2(g,tg+4) a3(g+8,tg+4)
//   B: b0(tg,g) b1(tg+4,g)
//   C: c0(g,2tg) c1(g,2tg+1) c2(g+8,2tg) c3(g+8,2tg+1)
// ---------------------------------------------------------------------------
__global__ __launch_bounds__(128) void attn_tc(const float* __restrict__ qkv,
                                               float* __restrict__ out)
{
    __shared__ float Kt[32][72];      // K^T (tf32 bits) [dim][key], 64 keys used
    __shared__ float Vs[64][40];      // V   (tf32 bits) [key][dim]
    __shared__ float Ps[4][32][36];   // per-warp P (tf32 bits) [row][key-chunk]

    const int blk = blockIdx.x;
    const int qt = blk & 7;
    const int h  = (blk >> 3) & 15;
    const int b  = blk >> 7;
    const int tid  = threadIdx.x;
    const int warp = tid >> 5, lane = tid & 31;
    const int g = lane >> 2, tg = lane & 3;

    const float* base = qkv + (size_t)b * NTOK * QKVW;
    const int qrow0 = qt * 128 + warp * 32;
    const float scale = 0.17677669529663687f;  // 32^-0.5

    // Q fragments (scaled, tf32), resident for the whole kernel
    uint32_t Qa[2][4][4];
#pragma unroll
    for (int mt = 0; mt < 2; mt++) {
        const float* r0 = base + (size_t)(qrow0 + mt * 16 + g) * QKVW + h * HD;
        const float* r1 = r0 + (size_t)8 * QKVW;
#pragma unroll
        for (int ks = 0; ks < 4; ks++) {
            Qa[mt][ks][0] = f2tf32(r0[ks * 8 + tg]     * scale);
            Qa[mt][ks][1] = f2tf32(r1[ks * 8 + tg]     * scale);
            Qa[mt][ks][2] = f2tf32(r0[ks * 8 + tg + 4] * scale);
            Qa[mt][ks][3] = f2tf32(r1[ks * 8 + tg + 4] * scale);
        }
    }

    float O[2][4][4];
#pragma unroll
    for (int mt = 0; mt < 2; mt++)
#pragma unroll
        for (int nt = 0; nt < 4; nt++)
#pragma unroll
            for (int r = 0; r < 4; r++) O[mt][nt][r] = 0.f;

    float mrow[4], lrow[4];
#pragma unroll
    for (int i = 0; i < 4; i++) { mrow[i] = -1e30f; lrow[i] = 0.f; }

    for (int kt = 0; kt < NTOK; kt += 64) {
        __syncthreads();
        // Stage 64 keys of K^T and V (converted to tf32 once here)
#pragma unroll
        for (int it = 0; it < 4; it++) {
            const int key = it * 16 + (tid >> 3);
            const int d4  = (tid & 7) * 4;
            const float* rp = base + (size_t)(kt + key) * QKVW + h * HD + d4;
            float4 kk = *(const float4*)(rp + C_DIM);
            float4 vv = *(const float4*)(rp + 2 * C_DIM);
            Kt[d4 + 0][key] = tf32r(kk.x);
            Kt[d4 + 1][key] = tf32r(kk.y);
            Kt[d4 + 2][key] = tf32r(kk.z);
            Kt[d4 + 3][key] = tf32r(kk.w);
            float4 vt;
            vt.x = tf32r(vv.x);
            vt.y = tf32r(vv.y);
            vt.z = tf32r(vv.z);
            vt.w = tf32r(vv.w);
            *(float4*)&Vs[key][d4] = vt;
        }
        __syncthreads();

#pragma unroll
        for (int sub = 0; sub < 2; sub++) {
            const int ko = sub * 32;

            // S = Q @ K^T  (32 rows x 32 keys per warp)
            float S[2][4][4];
#pragma unroll
            for (int mt = 0; mt < 2; mt++)
#pragma unroll
                for (int nt = 0; nt < 4; nt++)
#pragma unroll
                    for (int r = 0; r < 4; r++) S[mt][nt][r] = 0.f;

#pragma unroll
            for (int nt = 0; nt < 4; nt++) {
                const int col = ko + nt * 8 + g;
#pragma unroll
                for (int ks = 0; ks < 4; ks++) {
                    uint32_t b0 = __float_as_uint(Kt[ks * 8 + tg][col]);
                    uint32_t b1 = __float_as_uint(Kt[ks * 8 + tg + 4][col]);
                    mma_tf32(S[0][nt], Qa[0][ks], b0, b1);
                    mma_tf32(S[1][nt], Qa[1][ks], b0, b1);
                }
            }

            // Online softmax (row stats live in quads) + P -> smem (tf32)
#pragma unroll
            for (int mt = 0; mt < 2; mt++) {
                float m0 = fmaxf(fmaxf(S[mt][0][0], S[mt][0][1]),
                                 fmaxf(S[mt][1][0], S[mt][1][1]));
                m0 = fmaxf(m0, fmaxf(fmaxf(S[mt][2][0], S[mt][2][1]),
                                     fmaxf(S[mt][3][0], S[mt][3][1])));
                float m1 = fmaxf(fmaxf(S[mt][0][2], S[mt][0][3]),
                                 fmaxf(S[mt][1][2], S[mt][1][3]));
                m1 = fmaxf(m1, fmaxf(fmaxf(S[mt][2][2], S[mt][2][3]),
                                     fmaxf(S[mt][3][2], S[mt][3][3])));
                m0 = fmaxf(m0, __shfl_xor_sync(0xffffffffu, m0, 1));
                m0 = fmaxf(m0, __shfl_xor_sync(0xffffffffu, m0, 2));
                m1 = fmaxf(m1, __shfl_xor_sync(0xffffffffu, m1, 1));
                m1 = fmaxf(m1, __shfl_xor_sync(0xffffffffu, m1, 2));

                const int i0 = mt * 2, i1 = i0 + 1;
                const float nm0 = fmaxf(mrow[i0], m0);
                const float nm1 = fmaxf(mrow[i1], m1);
                const float c0 = __expf(mrow[i0] - nm0);
                const float c1 = __expf(mrow[i1] - nm1);
                mrow[i0] = nm0; mrow[i1] = nm1;

                float sum0 = 0.f, sum1 = 0.f;
#pragma unroll
                for (int nt = 0; nt < 4; nt++) {
                    float p0 = __expf(S[mt][nt][0] - nm0);
                    float p1 = __expf(S[mt][nt][1] - nm0);
                    float p2 = __expf(S[mt][nt][2] - nm1);
                    float p3 = __expf(S[mt][nt][3] - nm1);
                    sum0 += p0 + p1; sum1 += p2 + p3;
                    float2 lo, hi;
                    lo.x = tf32r(p0);
                    lo.y = tf32r(p1);
                    hi.x = tf32r(p2);
                    hi.y = tf32r(p3);
                    *(float2*)&Ps[warp][mt * 16 + g    ][nt * 8 + 2 * tg] = lo;
                    *(float2*)&Ps[warp][mt * 16 + g + 8][nt * 8 + 2 * tg] = hi;
                    O[mt][nt][0] *= c0; O[mt][nt][1] *= c0;
                    O[mt][nt][2] *= c1; O[mt][nt][3] *= c1;
                }
                sum0 += __shfl_xor_sync(0xffffffffu, sum0, 1);
                sum0 += __shfl_xor_sync(0xffffffffu, sum0, 2);
                sum1 += __shfl_xor_sync(0xffffffffu, sum1, 1);
                sum1 += __shfl_xor_sync(0xffffffffu, sum1, 2);
                lrow[i0] = lrow[i0] * c0 + sum0;
                lrow[i1] = lrow[i1] * c1 + sum1;
            }
            __syncwarp();

            // Reload P as A fragments (warp-private region; conflict-free)
            uint32_t Pa[2][4][4];
#pragma unroll
            for (int mt = 0; mt < 2; mt++)
#pragma unroll
                for (int ks = 0; ks < 4; ks++) {
                    Pa[mt][ks][0] = __float_as_uint(Ps[warp][mt * 16 + g    ][ks * 8 + tg]);
                    Pa[mt][ks][1] = __float_as_uint(Ps[warp][mt * 16 + g + 8][ks * 8 + tg]);
                    Pa[mt][ks][2] = __float_as_uint(Ps[warp][mt * 16 + g    ][ks * 8 + tg + 4]);
                    Pa[mt][ks][3] = __float_as_uint(Ps[warp][mt * 16 + g + 8][ks * 8 + tg + 4]);
                }

            // O += P @ V
#pragma unroll
            for (int nt = 0; nt < 4; nt++) {
                const int dc = nt * 8 + g;
#pragma unroll
                for (int ks = 0; ks < 4; ks++) {
                    uint32_t b0 = __float_as_uint(Vs[ko + ks * 8 + tg    ][dc]);
                    uint32_t b1 = __float_as_uint(Vs[ko + ks * 8 + tg + 4][dc]);
                    mma_tf32(O[0][nt], Pa[0][ks], b0, b1);
                    mma_tf32(O[1][nt], Pa[1][ks], b0, b1);
                }
            }
            __syncwarp();
        }
    }

    // Epilogue: normalize and write [B, N, C]
#pragma unroll
    for (int mt = 0; mt < 2; mt++) {
        const float inv0 = 1.f / lrow[mt * 2];
        const float inv1 = 1.f / lrow[mt * 2 + 1];
        const int r0 = qrow0 + mt * 16 + g;
        float* p0 = out + (size_t)(b * NTOK + r0) * C_DIM + h * HD;
        float* p1 = p0 + (size_t)8 * C_DIM;
#pragma unroll
        for (int nt = 0; nt < 4; nt++) {
            float2 o0 = make_float2(O[mt][nt][0] * inv0, O[mt][nt][1] * inv0);
            float2 o1 = make_float2(O[mt][nt][2] * inv1, O[mt][nt][3] * inv1);
            *(float2*)(p0 + nt * 8 + 2 * tg) = o0;
            *(float2*)(p1 + nt * 8 + 2 * tg) = o1;
        }
    }
}

// ---------------------------------------------------------------------------
// LePE: 5x5 depthwise conv on x (NHWC), zero padding, output in [B,N,C].
// ---------------------------------------------------------------------------
__global__ __launch_bounds__(256) void lepe_kernel(
    const float* __restrict__ x, const float* __restrict__ w,
    const float* __restrict__ bias, float* __restrict__ out)
{
    __shared__ float ws[256 * 25];
    const int tid = threadIdx.x;
    const int c0  = blockIdx.y * 256;
    for (int i = tid; i < 256 * 25; i += 256) ws[i] = w[c0 * 25 + i];
    __syncthreads();

    const int pos = blockIdx.x;
    const int c   = c0 + tid;
    const int b   = pos >> 10;
    const int y   = (pos >> 5) & 31;
    const int xx  = pos & 31;
    const float* wv = &ws[tid * 25];

    float acc = bias[c];
#pragma unroll
    for (int dy = 0; dy < 5; dy++) {
        const int yy = y + dy - 2;
        if ((unsigned)yy >= 32u) continue;
#pragma unroll
        for (int dx = 0; dx < 5; dx++) {
            const int xs = xx + dx - 2;
            if ((unsigned)xs >= 32u) continue;
            acc += x[(((size_t)b * IMG + yy) * IMG + xs) * C_DIM + c] * wv[dy * 5 + dx];
        }
    }
    out[(size_t)pos * C_DIM + c] = acc;
}

// ---------------------------------------------------------------------------
// Launch: qkv GEMM (tf32 TC) -> attention (tf32 TC) ; lepe ; proj (3xTF32 TC)
// ---------------------------------------------------------------------------
extern "C" void kernel_launch(void* const* d_in, const int* in_sizes, int n_in,
                              void* d_out, int out_size)
{
    const float* x      = (const float*)d_in[0];
    const float* w_qkv  = (const float*)d_in[1];
    const float* w_proj = (const float*)d_in[2];
    const float* b_proj = (const float*)d_in[3];
    const float* w_lepe = (const float*)d_in[4];
    const float* b_lepe = (const float*)d_in[5];
    float* out = (float*)d_out;

    float *qkv_buf, *attn_buf, *lepe_buf;
    cudaGetSymbolAddress((void**)&qkv_buf,  g_qkv);
    cudaGetSymbolAddress((void**)&attn_buf, g_attn);
    cudaGetSymbolAddress((void**)&lepe_buf, g_lepe);

    // 1) QKV GEMM (tf32 tensor cores): [8192,512] x [1536,512]^T -> [8192,1536]
    sgemm_tf32<<<dim3(QKVW / 128, MROWS / 128), 256>>>(
        x, w_qkv, qkv_buf, MROWS, QKVW, C_DIM);

    // 2) Flash attention (tf32 tensor cores) -> g_attn in [B,N,C] layout
    attn_tc<<<BATCH * HEADS * (NTOK / 128), 128>>>(qkv_buf, attn_buf);

    // 3) LePE depthwise conv -> g_lepe
    lepe_kernel<<<dim3(BATCH * IMG * IMG, C_DIM / 256), 256>>>(
        x, w_lepe, b_lepe, lepe_buf);

    // 4) Fused (attn + lepe) @ w_proj^T + b_proj -> out  (3xTF32, ~fp32 accuracy)
    sgemm_3xtf32<<<dim3(C_DIM / 128, MROWS / 128), 256>>>(
        attn_buf, lepe_buf, w_proj, b_proj, out, MROWS, C_DIM, C_DIM);
}

// round 12
// speedup vs baseline: 2.2686x; 1.0880x over previous
#include <cuda_runtime.h>
#include <cstdint>

// Problem constants (fixed shapes from reference)
#define C_DIM   512
#define HEADS   16
#define HD      32
#define BATCH   8
#define IMG     32
#define NTOK    1024            // IMG*IMG
#define MROWS   (BATCH * NTOK)  // 8192
#define QKVW    (3 * C_DIM)     // 1536

// Scratch (static device globals; allocation-free per harness rules)
__device__ float g_qkv [(size_t)MROWS * QKVW];   // ~50 MB
__device__ float g_attn[(size_t)MROWS * C_DIM];  // ~17 MB
__device__ float g_lepe[(size_t)MROWS * C_DIM];  // ~17 MB

// ---------------------------------------------------------------------------
// tf32 helpers
// ---------------------------------------------------------------------------
__device__ __forceinline__ uint32_t f2tf32(float f) {
    uint32_t u;
    asm("cvt.rna.tf32.f32 %0, %1;" : "=r"(u) : "f"(f));
    return u;
}
__device__ __forceinline__ float tf32r(float f) {
    return __uint_as_float(f2tf32(f));
}

__device__ __forceinline__ void mma_tf32(float* d, const uint32_t* a,
                                         uint32_t b0, uint32_t b1) {
    asm("mma.sync.aligned.m16n8k8.row.col.f32.tf32.tf32.f32 "
        "{%0,%1,%2,%3}, {%4,%5,%6,%7}, {%8,%9}, {%0,%1,%2,%3};"
        : "+f"(d[0]), "+f"(d[1]), "+f"(d[2]), "+f"(d[3])
        : "r"(a[0]), "r"(a[1]), "r"(a[2]), "r"(a[3]), "r"(b0), "r"(b1));
}

// ---------------------------------------------------------------------------
// TF32 tensor-core GEMM (NT): C[m,n] = sum_k (A[m,k] [+A2[m,k]]) * W[n,k] [+bias]
// A2/bias may be nullptr. Used for BOTH qkv (A2=bias=null) and proj.
// 256 threads = 8 warps (4 m x 2 n), warp tile 32x64, block tile 128x128.
// BK=16, double-buffered smem stored K-major [k][m], stride 136
// (136 % 32 == 8 -> fragment loads hit 32 distinct banks).
// Operands rounded to tf32 (rna) at smem fill.
// ---------------------------------------------------------------------------
__global__ __launch_bounds__(256) void sgemm_tf32(
    const float* __restrict__ A, const float* __restrict__ A2,
    const float* __restrict__ W, const float* __restrict__ bias,
    float* __restrict__ C, int M, int Nn, int K)
{
    __shared__ float As[2][16][136];
    __shared__ float Bs[2][16][136];

    const int tid  = threadIdx.x;
    const int warp = tid >> 5, lane = tid & 31;
    const int g = lane >> 2, tg = lane & 3;
    const int wm = warp & 3, wn = warp >> 2;
    const int m0 = blockIdx.y * 128, n0 = blockIdx.x * 128;

    const int lr = tid >> 1;          // 0..127
    const int lk = (tid & 1) * 8;     // 0 or 8

    const float* Aptr  = A + (size_t)(m0 + lr) * K + lk;
    const float* A2ptr = A2 ? (A2 + (size_t)(m0 + lr) * K + lk) : nullptr;
    const float* Wptr  = W + (size_t)(n0 + lr) * K + lk;

    float acc[2][8][4];
#pragma unroll
    for (int mt = 0; mt < 2; mt++)
#pragma unroll
        for (int nt = 0; nt < 8; nt++)
#pragma unroll
            for (int r = 0; r < 4; r++) acc[mt][nt][r] = 0.f;

#define STASH(buf, a0v, a1v, w0v, w1v)                                   \
    do {                                                                 \
        As[buf][lk + 0][lr] = tf32r((a0v).x);                            \
        As[buf][lk + 1][lr] = tf32r((a0v).y);                            \
        As[buf][lk + 2][lr] = tf32r((a0v).z);                            \
        As[buf][lk + 3][lr] = tf32r((a0v).w);                            \
        As[buf][lk + 4][lr] = tf32r((a1v).x);                            \
        As[buf][lk + 5][lr] = tf32r((a1v).y);                            \
        As[buf][lk + 6][lr] = tf32r((a1v).z);                            \
        As[buf][lk + 7][lr] = tf32r((a1v).w);                            \
        Bs[buf][lk + 0][lr] = tf32r((w0v).x);                            \
        Bs[buf][lk + 1][lr] = tf32r((w0v).y);                            \
        Bs[buf][lk + 2][lr] = tf32r((w0v).z);                            \
        Bs[buf][lk + 3][lr] = tf32r((w0v).w);                            \
        Bs[buf][lk + 4][lr] = tf32r((w1v).x);                            \
        Bs[buf][lk + 5][lr] = tf32r((w1v).y);                            \
        Bs[buf][lk + 6][lr] = tf32r((w1v).z);                            \
        Bs[buf][lk + 7][lr] = tf32r((w1v).w);                            \
    } while (0)

#define LOADAB(k0, a0v, a1v, w0v, w1v)                                   \
    do {                                                                 \
        a0v = *(const float4*)(Aptr + (k0));                             \
        a1v = *(const float4*)(Aptr + (k0) + 4);                         \
        if (A2ptr) {                                                     \
            float4 y0 = *(const float4*)(A2ptr + (k0));                  \
            float4 y1 = *(const float4*)(A2ptr + (k0) + 4);              \
            a0v.x += y0.x; a0v.y += y0.y; a0v.z += y0.z; a0v.w += y0.w;  \
            a1v.x += y1.x; a1v.y += y1.y; a1v.z += y1.z; a1v.w += y1.w;  \
        }                                                                \
        w0v = *(const float4*)(Wptr + (k0));                             \
        w1v = *(const float4*)(Wptr + (k0) + 4);                         \
    } while (0)

    {
        float4 a0, a1, w0, w1;
        LOADAB(0, a0, a1, w0, w1);
        STASH(0, a0, a1, w0, w1);
    }
    __syncthreads();

    int cur = 0;
    for (int k0 = 16; k0 <= K; k0 += 16) {
        const bool more = (k0 < K);
        float4 a0, a1, w0, w1;
        if (more) LOADAB(k0, a0, a1, w0, w1);

#pragma unroll
        for (int ks = 0; ks < 2; ks++) {
            const int kr0 = ks * 8 + tg, kr1 = kr0 + 4;
            uint32_t Af[2][4];
#pragma unroll
            for (int mt = 0; mt < 2; mt++) {
                const int mb = wm * 32 + mt * 16;
                Af[mt][0] = __float_as_uint(As[cur][kr0][mb + g]);
                Af[mt][1] = __float_as_uint(As[cur][kr0][mb + g + 8]);
                Af[mt][2] = __float_as_uint(As[cur][kr1][mb + g]);
                Af[mt][3] = __float_as_uint(As[cur][kr1][mb + g + 8]);
            }
            uint32_t Bf[8][2];
#pragma unroll
            for (int nt = 0; nt < 8; nt++) {
                const int cb = wn * 64 + nt * 8 + g;
                Bf[nt][0] = __float_as_uint(Bs[cur][kr0][cb]);
                Bf[nt][1] = __float_as_uint(Bs[cur][kr1][cb]);
            }
#pragma unroll
            for (int mt = 0; mt < 2; mt++)
#pragma unroll
                for (int nt = 0; nt < 8; nt++)
                    mma_tf32(acc[mt][nt], Af[mt], Bf[nt][0], Bf[nt][1]);
        }

        if (more) {
            STASH(cur ^ 1, a0, a1, w0, w1);
            __syncthreads();
            cur ^= 1;
        }
    }
#undef STASH
#undef LOADAB

    // Epilogue: C-fragment rows g / g+8, cols nt*8 + 2tg (+1); optional bias
#pragma unroll
    for (int mt = 0; mt < 2; mt++) {
        const int r0 = m0 + wm * 32 + mt * 16 + g;
        float* c0 = C + (size_t)r0 * Nn + n0 + wn * 64;
        float* c1 = c0 + (size_t)8 * Nn;
#pragma unroll
        for (int nt = 0; nt < 8; nt++) {
            float b0v = 0.f, b1v = 0.f;
            if (bias) {
                const int cc = n0 + wn * 64 + nt * 8 + 2 * tg;
                b0v = bias[cc]; b1v = bias[cc + 1];
            }
            *(float2*)(c0 + nt * 8 + 2 * tg) =
                make_float2(acc[mt][nt][0] + b0v, acc[mt][nt][1] + b1v);
            *(float2*)(c1 + nt * 8 + 2 * tg) =
                make_float2(acc[mt][nt][2] + b0v, acc[mt][nt][3] + b1v);
        }
    }
}

// ---------------------------------------------------------------------------
// Flash attention on tf32 tensor cores (mma.sync m16n8k8).
// Block = (b, h, 128-query tile); 4 warps x 32 query rows.
// K stored transposed [dim][key] stride 72, V natural [key][dim] stride 40,
// P staged per-warp [row][key] stride 36 (all conflict-free on fragment ops).
// One softmax pass per 64-key tile: S for all 64 keys is computed first,
// then a single max/rescale/exp pass (stats via quad shuffles); only the
// cheap P-store/reload/P@V runs per 32-key half (keeps Ps within smem).
// Operands are RAW fp32 bits (hardware truncates to tf32).
// fragment layout (m16n8k8): g=lane>>2, tg=lane&3
//   A: a0(g,tg) a1(g+8,tg) a2(g,tg+4) a3(g+8,tg+4)
//   B: b0(tg,g) b1(tg+4,g)
//   C: c0(g,2tg) c1(g,2tg+1) c2(g+8,2tg) c3(g+8,2tg+1)
// ---------------------------------------------------------------------------
__global__ __launch_bounds__(128) void attn_tc(const float* __restrict__ qkv,
                                               float* __restrict__ out)
{
    __shared__ float Kt[32][72];      // K^T [dim][key], 64 keys used
    __shared__ float Vs[64][40];      // V   [key][dim]
    __shared__ float Ps[4][32][36];   // per-warp P [row][32-key half]

    const int blk = blockIdx.x;
    const int qt = blk & 7;
    const int h  = (blk >> 3) & 15;
    const int b  = blk >> 7;
    const int tid  = threadIdx.x;
    const int warp = tid >> 5, lane = tid & 31;
    const int g = lane >> 2, tg = lane & 3;

    const float* base = qkv + (size_t)b * NTOK * QKVW;
    const int qrow0 = qt * 128 + warp * 32;
    const float scale = 0.17677669529663687f;  // 32^-0.5

    // Q fragments (scaled), resident for the whole kernel
    uint32_t Qa[2][4][4];
#pragma unroll
    for (int mt = 0; mt < 2; mt++) {
        const float* r0 = base + (size_t)(qrow0 + mt * 16 + g) * QKVW + h * HD;
        const float* r1 = r0 + (size_t)8 * QKVW;
#pragma unroll
        for (int ks = 0; ks < 4; ks++) {
            Qa[mt][ks][0] = __float_as_uint(r0[ks * 8 + tg]     * scale);
            Qa[mt][ks][1] = __float_as_uint(r1[ks * 8 + tg]     * scale);
            Qa[mt][ks][2] = __float_as_uint(r0[ks * 8 + tg + 4] * scale);
            Qa[mt][ks][3] = __float_as_uint(r1[ks * 8 + tg + 4] * scale);
        }
    }

    float O[2][4][4];
#pragma unroll
    for (int mt = 0; mt < 2; mt++)
#pragma unroll
        for (int nt = 0; nt < 4; nt++)
#pragma unroll
            for (int r = 0; r < 4; r++) O[mt][nt][r] = 0.f;

    float mrow[4], lrow[4];
#pragma unroll
    for (int i = 0; i < 4; i++) { mrow[i] = -1e30f; lrow[i] = 0.f; }

    for (int kt = 0; kt < NTOK; kt += 64) {
        __syncthreads();
        // Stage 64 keys of K^T and V (raw fp32 bits)
#pragma unroll
        for (int it = 0; it < 4; it++) {
            const int key = it * 16 + (tid >> 3);
            const int d4  = (tid & 7) * 4;
            const float* rp = base + (size_t)(kt + key) * QKVW + h * HD + d4;
            float4 kk = *(const float4*)(rp + C_DIM);
            float4 vv = *(const float4*)(rp + 2 * C_DIM);
            Kt[d4 + 0][key] = kk.x;
            Kt[d4 + 1][key] = kk.y;
            Kt[d4 + 2][key] = kk.z;
            Kt[d4 + 3][key] = kk.w;
            *(float4*)&Vs[key][d4] = vv;
        }
        __syncthreads();

        // S = Q @ K^T over ALL 64 keys (32 rows x 64 keys per warp)
        float S[2][8][4];
#pragma unroll
        for (int mt = 0; mt < 2; mt++)
#pragma unroll
            for (int nt = 0; nt < 8; nt++)
#pragma unroll
                for (int r = 0; r < 4; r++) S[mt][nt][r] = 0.f;

#pragma unroll
        for (int nt = 0; nt < 8; nt++) {
            const int col = nt * 8 + g;
#pragma unroll
            for (int ks = 0; ks < 4; ks++) {
                uint32_t b0 = __float_as_uint(Kt[ks * 8 + tg][col]);
                uint32_t b1 = __float_as_uint(Kt[ks * 8 + tg + 4][col]);
                mma_tf32(S[0][nt], Qa[0][ks], b0, b1);
                mma_tf32(S[1][nt], Qa[1][ks], b0, b1);
            }
        }

        // ONE softmax pass per 64-key tile; S is overwritten with P = exp(S-m)
#pragma unroll
        for (int mt = 0; mt < 2; mt++) {
            float m0 = -1e30f, m1 = -1e30f;
#pragma unroll
            for (int nt = 0; nt < 8; nt++) {
                m0 = fmaxf(m0, fmaxf(S[mt][nt][0], S[mt][nt][1]));
                m1 = fmaxf(m1, fmaxf(S[mt][nt][2], S[mt][nt][3]));
            }
            m0 = fmaxf(m0, __shfl_xor_sync(0xffffffffu, m0, 1));
            m0 = fmaxf(m0, __shfl_xor_sync(0xffffffffu, m0, 2));
            m1 = fmaxf(m1, __shfl_xor_sync(0xffffffffu, m1, 1));
            m1 = fmaxf(m1, __shfl_xor_sync(0xffffffffu, m1, 2));

            const int i0 = mt * 2, i1 = i0 + 1;
            const float nm0 = fmaxf(mrow[i0], m0);
            const float nm1 = fmaxf(mrow[i1], m1);
            const float c0 = __expf(mrow[i0] - nm0);
            const float c1 = __expf(mrow[i1] - nm1);
            mrow[i0] = nm0; mrow[i1] = nm1;

            float sum0 = 0.f, sum1 = 0.f;
#pragma unroll
            for (int nt = 0; nt < 8; nt++) {
                S[mt][nt][0] = __expf(S[mt][nt][0] - nm0);
                S[mt][nt][1] = __expf(S[mt][nt][1] - nm0);
                S[mt][nt][2] = __expf(S[mt][nt][2] - nm1);
                S[mt][nt][3] = __expf(S[mt][nt][3] - nm1);
                sum0 += S[mt][nt][0] + S[mt][nt][1];
                sum1 += S[mt][nt][2] + S[mt][nt][3];
            }
#pragma unroll
            for (int nt = 0; nt < 4; nt++) {
                O[mt][nt][0] *= c0; O[mt][nt][1] *= c0;
                O[mt][nt][2] *= c1; O[mt][nt][3] *= c1;
            }
            sum0 += __shfl_xor_sync(0xffffffffu, sum0, 1);
            sum0 += __shfl_xor_sync(0xffffffffu, sum0, 2);
            sum1 += __shfl_xor_sync(0xffffffffu, sum1, 1);
            sum1 += __shfl_xor_sync(0xffffffffu, sum1, 2);
            lrow[i0] = lrow[i0] * c0 + sum0;
            lrow[i1] = lrow[i1] * c1 + sum1;
        }

        // P@V per 32-key half (store P half -> reload as A frags -> mma)
#pragma unroll
        for (int sub = 0; sub < 2; sub++) {
            const int ko = sub * 32;
            const int nb = sub * 4;
            __syncwarp();
#pragma unroll
            for (int mt = 0; mt < 2; mt++)
#pragma unroll
                for (int nt = 0; nt < 4; nt++) {
                    *(float2*)&Ps[warp][mt * 16 + g    ][nt * 8 + 2 * tg] =
                        make_float2(S[mt][nb + nt][0], S[mt][nb + nt][1]);
                    *(float2*)&Ps[warp][mt * 16 + g + 8][nt * 8 + 2 * tg] =
                        make_float2(S[mt][nb + nt][2], S[mt][nb + nt][3]);
                }
            __syncwarp();

            uint32_t Pa[2][4][4];
#pragma unroll
            for (int mt = 0; mt < 2; mt++)
#pragma unroll
                for (int ks = 0; ks < 4; ks++) {
                    Pa[mt][ks][0] = __float_as_uint(Ps[warp][mt * 16 + g    ][ks * 8 + tg]);
                    Pa[mt][ks][1] = __float_as_uint(Ps[warp][mt * 16 + g + 8][ks * 8 + tg]);
                    Pa[mt][ks][2] = __float_as_uint(Ps[warp][mt * 16 + g    ][ks * 8 + tg + 4]);
                    Pa[mt][ks][3] = __float_as_uint(Ps[warp][mt * 16 + g + 8][ks * 8 + tg + 4]);
                }

#pragma unroll
            for (int nt = 0; nt < 4; nt++) {
                const int dc = nt * 8 + g;
#pragma unroll
                for (int ks = 0; ks < 4; ks++) {
                    uint32_t b0 = __float_as_uint(Vs[ko + ks * 8 + tg    ][dc]);
                    uint32_t b1 = __float_as_uint(Vs[ko + ks * 8 + tg + 4][dc]);
                    mma_tf32(O[0][nt], Pa[0][ks], b0, b1);
                    mma_tf32(O[1][nt], Pa[1][ks], b0, b1);
                }
            }
        }
    }

    // Epilogue: normalize and write [B, N, C]
#pragma unroll
    for (int mt = 0; mt < 2; mt++) {
        const float inv0 = 1.f / lrow[mt * 2];
        const float inv1 = 1.f / lrow[mt * 2 + 1];
        const int r0 = qrow0 + mt * 16 + g;
        float* p0 = out + (size_t)(b * NTOK + r0) * C_DIM + h * HD;
        float* p1 = p0 + (size_t)8 * C_DIM;
#pragma unroll
        for (int nt = 0; nt < 4; nt++) {
            float2 o0 = make_float2(O[mt][nt][0] * inv0, O[mt][nt][1] * inv0);
            float2 o1 = make_float2(O[mt][nt][2] * inv1, O[mt][nt][3] * inv1);
            *(float2*)(p0 + nt * 8 + 2 * tg) = o0;
            *(float2*)(p1 + nt * 8 + 2 * tg) = o1;
        }
    }
}

// ---------------------------------------------------------------------------
// LePE: 5x5 depthwise conv on x (NHWC), zero padding, output in [B,N,C].
// ---------------------------------------------------------------------------
__global__ __launch_bounds__(256) void lepe_kernel(
    const float* __restrict__ x, const float* __restrict__ w,
    const float* __restrict__ bias, float* __restrict__ out)
{
    __shared__ float ws[256 * 25];
    const int tid = threadIdx.x;
    const int c0  = blockIdx.y * 256;
    for (int i = tid; i < 256 * 25; i += 256) ws[i] = w[c0 * 25 + i];
    __syncthreads();

    const int pos = blockIdx.x;
    const int c   = c0 + tid;
    const int b   = pos >> 10;
    const int y   = (pos >> 5) & 31;
    const int xx  = pos & 31;
    const float* wv = &ws[tid * 25];

    float acc = bias[c];
#pragma unroll
    for (int dy = 0; dy < 5; dy++) {
        const int yy = y + dy - 2;
        if ((unsigned)yy >= 32u) continue;
#pragma unroll
        for (int dx = 0; dx < 5; dx++) {
            const int xs = xx + dx - 2;
            if ((unsigned)xs >= 32u) continue;
            acc += x[(((size_t)b * IMG + yy) * IMG + xs) * C_DIM + c] * wv[dy * 5 + dx];
        }
    }
    out[(size_t)pos * C_DIM + c] = acc;
}

// ---------------------------------------------------------------------------
// Launch: qkv GEMM (tf32 TC) -> attention (tf32 TC) ; lepe ; proj (tf32 TC fused)
// ---------------------------------------------------------------------------
extern "C" void kernel_launch(void* const* d_in, const int* in_sizes, int n_in,
                              void* d_out, int out_size)
{
    const float* x      = (const float*)d_in[0];
    const float* w_qkv  = (const float*)d_in[1];
    const float* w_proj = (const float*)d_in[2];
    const float* b_proj = (const float*)d_in[3];
    const float* w_lepe = (const float*)d_in[4];
    const float* b_lepe = (const float*)d_in[5];
    float* out = (float*)d_out;

    float *qkv_buf, *attn_buf, *lepe_buf;
    cudaGetSymbolAddress((void**)&qkv_buf,  g_qkv);
    cudaGetSymbolAddress((void**)&attn_buf, g_attn);
    cudaGetSymbolAddress((void**)&lepe_buf, g_lepe);

    // 1) QKV GEMM (tf32 tensor cores): [8192,512] x [1536,512]^T -> [8192,1536]
    sgemm_tf32<<<dim3(QKVW / 128, MROWS / 128), 256>>>(
        x, nullptr, w_qkv, nullptr, qkv_buf, MROWS, QKVW, C_DIM);

    // 2) Flash attention (tf32 tensor cores) -> g_attn in [B,N,C] layout
    attn_tc<<<BATCH * HEADS * (NTOK / 128), 128>>>(qkv_buf, attn_buf);

    // 3) LePE depthwise conv -> g_lepe
    lepe_kernel<<<dim3(BATCH * IMG * IMG, C_DIM / 256), 256>>>(
        x, w_lepe, b_lepe, lepe_buf);

    // 4) Fused (attn + lepe) @ w_proj^T + b_proj -> out (tf32 TC, double-buffered)
    sgemm_tf32<<<dim3(C_DIM / 128, MROWS / 128), 256>>>(
        attn_buf, lepe_buf, w_proj, b_proj, out, MROWS, C_DIM, C_DIM);
}